// round 8
// baseline (speedup 1.0000x reference)
#include <cuda_runtime.h>
#include <cstdint>

#define BATCH   8
#define SEQL    2048
#define NUM_SUB 16
#define CBSZ    1024
#define SUBD    64
#define NTOK    (BATCH * SEQL)       // 16384
#define EMBD    (NUM_SUB * SUBD)     // 1024
#define CHUNK   128                  // codewords staged per iteration (32 KB)
#define KTILE   4                    // codeword chains in flight per thread
#define TPB     256                  // threads per block; 1 (token,m) per thread

// sum of squares of 64 floats replicating XLA:GPU row-reduce (warp-per-row):
// thread t accumulates strided elements t and t+32 (coalesced loop k += 32):
//   leaf_t = rn(rn(v[t]^2) + rn(v[t+32]^2))
// then shfl.down butterfly: offsets 16, 8, 4, 2, 1, each add rounded.
__device__ __forceinline__ float sumsq_xla64(const float* __restrict__ v) {
    float p[32];
#pragma unroll
    for (int t = 0; t < 32; t++)
        p[t] = __fadd_rn(__fmul_rn(v[t], v[t]),
                         __fmul_rn(v[t + 32], v[t + 32]));
#pragma unroll
    for (int off = 16; off >= 1; off >>= 1)
#pragma unroll 32
        for (int t = 0; t < off; t++)
            p[t] = __fadd_rn(p[t], p[t + off]);
    return p[0];
}

// out: [quantized 16777216 f32][indices 262144 f32]
__global__ __launch_bounds__(TPB, 2)
void pq_argmin_kernel(const float* __restrict__ emb,
                      const float* __restrict__ cb,
                      float*       __restrict__ out)
{
    __shared__ float4 scw[CHUNK * (SUBD / 4)];  // codeword chunk: 32 KB
    __shared__ float  sc2[CBSZ];                // ||c||^2 (XLA rounding): 4 KB

    const int m   = blockIdx.y;
    const int tok = blockIdx.x * TPB + threadIdx.x;
    const int tid = threadIdx.x;

    const float* cbm = cb + (size_t)m * CBSZ * SUBD;

    // ---- token subvector into registers ----
    float x[SUBD];
    {
        const float4* p = (const float4*)(emb + (size_t)tok * EMBD + m * SUBD);
#pragma unroll
        for (int i = 0; i < 16; i++) {
            float4 v = p[i];
            x[4*i] = v.x; x[4*i+1] = v.y; x[4*i+2] = v.z; x[4*i+3] = v.w;
        }
    }
    // x2 = sum(x*x): XLA warp-row-reduce rounding (strided-32 leaves + butterfly)
    const float x2 = sumsq_xla64(x);

    // ---- c2 for all 1024 codewords, same XLA rounding ----
    for (int k = tid; k < CBSZ; k += TPB) {
        float cv[SUBD];
        const float4* cr = (const float4*)(cbm + (size_t)k * SUBD);
#pragma unroll
        for (int i = 0; i < 16; i++) {
            float4 v = cr[i];
            cv[4*i] = v.x; cv[4*i+1] = v.y; cv[4*i+2] = v.z; cv[4*i+3] = v.w;
        }
        sc2[k] = sumsq_xla64(cv);
    }

    float best = 3.402823466e38f;
    int   bk   = 0;

    for (int c0 = 0; c0 < CBSZ; c0 += CHUNK) {
        __syncthreads();   // prev chunk consumed (also orders sc2 on first pass)
        {
            const float4* src = (const float4*)(cbm + (size_t)c0 * SUBD);
#pragma unroll
            for (int i = 0; i < (CHUNK * SUBD / 4) / TPB; i++)
                scw[tid + i * TPB] = src[tid + i * TPB];
        }
        __syncthreads();

        for (int kt = 0; kt < CHUNK / KTILE; kt++) {
            // KTILE independent chains; each: sequential FMA ascending j
            // (bit-matches cublas SIMT sgemm per-output accumulation)
            float acc[KTILE];
#pragma unroll
            for (int q = 0; q < KTILE; q++) acc[q] = 0.f;

            const float4* tb = scw + (kt * KTILE) * (SUBD / 4);
#pragma unroll
            for (int i = 0; i < SUBD / 4; i++) {
#pragma unroll
                for (int q = 0; q < KTILE; q++) {
                    float4 c = tb[q * (SUBD / 4) + i];   // broadcast LDS.128
                    acc[q] = __fmaf_rn(x[4*i],     c.x, acc[q]);
                    acc[q] = __fmaf_rn(x[4*i + 1], c.y, acc[q]);
                    acc[q] = __fmaf_rn(x[4*i + 2], c.z, acc[q]);
                    acc[q] = __fmaf_rn(x[4*i + 3], c.w, acc[q]);
                }
            }
#pragma unroll
            for (int q = 0; q < KTILE; q++) {
                int   k = c0 + kt * KTILE + q;
                // dist = rn(rn(x2 - rn(2*xc)) + c2), 2*xc exact
                float dist = __fadd_rn(__fsub_rn(x2, __fmul_rn(2.0f, acc[q])), sc2[k]);
                if (dist < best) { best = dist; bk = k; }  // strict <: first-index ties
            }
        }
    }

    // ---- gather winner + write outputs ----
    const size_t QELEMS = (size_t)NTOK * EMBD;
    {
        const float4* w = (const float4*)(cbm + (size_t)bk * SUBD);
        float4* q = (float4*)(out + (size_t)tok * EMBD + m * SUBD);
#pragma unroll
        for (int i = 0; i < 16; i++) q[i] = w[i];
        out[QELEMS + (size_t)tok * NUM_SUB + m] = (float)bk;
    }
}

extern "C" void kernel_launch(void* const* d_in, const int* in_sizes, int n_in,
                              void* d_out, int out_size)
{
    const float* emb = (const float*)d_in[0];  // [8,2048,1024] f32
    const float* cb  = (const float*)d_in[1];  // [16,1024,64]  f32
    dim3 grid(NTOK / TPB, NUM_SUB);            // (64, 16)
    pq_argmin_kernel<<<grid, TPB>>>(emb, cb, (float*)d_out);
}

// round 10
// speedup vs baseline: 1.0575x; 1.0575x over previous
#include <cuda_runtime.h>
#include <cstdint>

#define BATCH   8
#define SEQL    2048
#define NUM_SUB 16
#define CBSZ    1024
#define SUBD    64
#define NTOK    (BATCH * SEQL)       // 16384
#define EMBD    (NUM_SUB * SUBD)     // 1024
#define CHUNK   128                  // codewords staged per iteration (32 KB)
#define KTILE   4                    // codeword chains in flight per thread
#define TPB     128                  // threads per block; 2 tokens per thread

// ---------- packed f32x2 helpers ----------
__device__ __forceinline__ unsigned long long pk2(float lo, float hi) {
    unsigned long long r;
    asm("mov.b64 %0, {%1, %2};" : "=l"(r) : "f"(lo), "f"(hi));
    return r;
}
__device__ __forceinline__ unsigned long long ffma2(unsigned long long a,
                                                    unsigned long long b,
                                                    unsigned long long c) {
    unsigned long long d;
    asm("fma.rn.f32x2 %0, %1, %2, %3;" : "=l"(d) : "l"(a), "l"(b), "l"(c));
    return d;
}
__device__ __forceinline__ void unpk2(unsigned long long a, float& lo, float& hi) {
    unsigned int l, h;
    asm("mov.b64 {%0, %1}, %2;" : "=r"(l), "=r"(h) : "l"(a));
    lo = __uint_as_float(l); hi = __uint_as_float(h);
}

// sum of squares of 64 floats replicating XLA:GPU warp-per-row reduce:
// leaf_t = rn(rn(v[t]^2) + rn(v[t+32]^2)); shfl.down butterfly 16,8,4,2,1.
// (R8-proven bit scheme — do not alter.)
__device__ __forceinline__ float sumsq_xla64(const float* __restrict__ v) {
    float p[32];
#pragma unroll
    for (int t = 0; t < 32; t++)
        p[t] = __fadd_rn(__fmul_rn(v[t], v[t]),
                         __fmul_rn(v[t + 32], v[t + 32]));
#pragma unroll
    for (int off = 16; off >= 1; off >>= 1)
#pragma unroll 32
        for (int t = 0; t < off; t++)
            p[t] = __fadd_rn(p[t], p[t + off]);
    return p[0];
}

// out: [quantized 16777216 f32][indices 262144 f32]
__global__ __launch_bounds__(TPB, 2)
void pq_argmin_kernel(const float* __restrict__ emb,
                      const float* __restrict__ cb,
                      float*       __restrict__ out)
{
    __shared__ float4 scw[CHUNK * (SUBD / 4)];  // codeword chunk: 32 KB
    __shared__ float  sc2[CBSZ];                // ||c||^2 (XLA rounding): 4 KB

    const int m   = blockIdx.y;
    const int tid = threadIdx.x;
    const int t0  = blockIdx.x * (2 * TPB) + tid;
    const int t1  = t0 + TPB;

    const float* cbm = cb + (size_t)m * CBSZ * SUBD;

    // ---- load both tokens; exact-XLA x2; pack (2j, 2j+1) f32x2 pairs ----
    unsigned long long xp0[SUBD / 2], xp1[SUBD / 2];
    float x2_0, x2_1;
    {
        float xs[SUBD];
        const float4* p = (const float4*)(emb + (size_t)t0 * EMBD + m * SUBD);
#pragma unroll
        for (int i = 0; i < 16; i++) {
            float4 v = p[i];
            xs[4*i] = v.x; xs[4*i+1] = v.y; xs[4*i+2] = v.z; xs[4*i+3] = v.w;
        }
        x2_0 = sumsq_xla64(xs);
#pragma unroll
        for (int j = 0; j < SUBD / 2; j++) xp0[j] = pk2(xs[2*j], xs[2*j+1]);
    }
    {
        float xs[SUBD];
        const float4* p = (const float4*)(emb + (size_t)t1 * EMBD + m * SUBD);
#pragma unroll
        for (int i = 0; i < 16; i++) {
            float4 v = p[i];
            xs[4*i] = v.x; xs[4*i+1] = v.y; xs[4*i+2] = v.z; xs[4*i+3] = v.w;
        }
        x2_1 = sumsq_xla64(xs);
#pragma unroll
        for (int j = 0; j < SUBD / 2; j++) xp1[j] = pk2(xs[2*j], xs[2*j+1]);
    }

    // ---- c2 for all 1024 codewords, exact XLA scheme (R8-proven) ----
    for (int k = tid; k < CBSZ; k += TPB) {
        float cv[SUBD];
        const float4* cr = (const float4*)(cbm + (size_t)k * SUBD);
#pragma unroll
        for (int i = 0; i < 16; i++) {
            float4 v = cr[i];
            cv[4*i] = v.x; cv[4*i+1] = v.y; cv[4*i+2] = v.z; cv[4*i+3] = v.w;
        }
        sc2[k] = sumsq_xla64(cv);
    }

    // top-4 screening candidates per token (sorted ascending)
    float bdA[4] = {3.4e38f, 3.4e38f, 3.4e38f, 3.4e38f};
    float bdB[4] = {3.4e38f, 3.4e38f, 3.4e38f, 3.4e38f};
    int   biA[4] = {0, 0, 0, 0};
    int   biB[4] = {0, 0, 0, 0};

    for (int c0 = 0; c0 < CBSZ; c0 += CHUNK) {
        __syncthreads();   // prev chunk consumed (orders sc2 on first pass too)
        {
            const float4* src = (const float4*)(cbm + (size_t)c0 * SUBD);
#pragma unroll
            for (int i = 0; i < (CHUNK * SUBD / 4) / TPB; i++)
                scw[tid + i * TPB] = src[tid + i * TPB];
        }
        __syncthreads();

        // One codeword = 64 floats = 256 bytes = 16 ulonglong2.
        const ulonglong2* cw2 = (const ulonglong2*)scw;

        for (int kt = 0; kt < CHUNK / KTILE; kt++) {
            unsigned long long acc[2 * KTILE];   // [2q]=tok0, [2q+1]=tok1
#pragma unroll
            for (int q = 0; q < 2 * KTILE; q++) acc[q] = 0ull;

            const ulonglong2* tb = cw2 + (kt * KTILE) * 16;
#pragma unroll
            for (int i = 0; i < 16; i++) {       // 16 steps x 4 floats = 64 dims
#pragma unroll
                for (int q = 0; q < KTILE; q++) {
                    ulonglong2 ca = tb[q * 16 + i]; // (c[4i],c[4i+1]),(c[4i+2],c[4i+3])
                    acc[2*q]   = ffma2(xp0[2*i],   ca.x, acc[2*q]);
                    acc[2*q]   = ffma2(xp0[2*i+1], ca.y, acc[2*q]);
                    acc[2*q+1] = ffma2(xp1[2*i],   ca.x, acc[2*q+1]);
                    acc[2*q+1] = ffma2(xp1[2*i+1], ca.y, acc[2*q+1]);
                }
            }
#pragma unroll
            for (int q = 0; q < KTILE; q++) {
                int   k = c0 + kt * KTILE + q;
                float l0, h0, l1, h1;
                unpk2(acc[2*q],   l0, h0);
                unpk2(acc[2*q+1], l1, h1);
                float d0 = __fadd_rn(l0, h0);
                float d1 = __fadd_rn(l1, h1);
                float c2 = sc2[k];
                float da = __fadd_rn(__fsub_rn(x2_0, __fmul_rn(2.0f, d0)), c2);
                float db = __fadd_rn(__fsub_rn(x2_1, __fmul_rn(2.0f, d1)), c2);
                if (da < bdA[3]) {
                    if (da < bdA[0])      { bdA[3]=bdA[2]; biA[3]=biA[2]; bdA[2]=bdA[1]; biA[2]=biA[1]; bdA[1]=bdA[0]; biA[1]=biA[0]; bdA[0]=da; biA[0]=k; }
                    else if (da < bdA[1]) { bdA[3]=bdA[2]; biA[3]=biA[2]; bdA[2]=bdA[1]; biA[2]=biA[1]; bdA[1]=da; biA[1]=k; }
                    else if (da < bdA[2]) { bdA[3]=bdA[2]; biA[3]=biA[2]; bdA[2]=da; biA[2]=k; }
                    else                  { bdA[3]=da; biA[3]=k; }
                }
                if (db < bdB[3]) {
                    if (db < bdB[0])      { bdB[3]=bdB[2]; biB[3]=biB[2]; bdB[2]=bdB[1]; biB[2]=biB[1]; bdB[1]=bdB[0]; biB[1]=biB[0]; bdB[0]=db; biB[0]=k; }
                    else if (db < bdB[1]) { bdB[3]=bdB[2]; biB[3]=biB[2]; bdB[2]=bdB[1]; biB[2]=biB[1]; bdB[1]=db; biB[1]=k; }
                    else if (db < bdB[2]) { bdB[3]=bdB[2]; biB[3]=biB[2]; bdB[2]=db; biB[2]=k; }
                    else                  { bdB[3]=db; biB[3]=k; }
                }
            }
        }
    }

    // ---- exact rescore (R8 bit-scheme) of top-4 candidates per token ----
    int winA, winB;
    {
        float bd = 3.4e38f; int bk = 0x7fffffff;
#pragma unroll 1
        for (int i = 0; i < 4; i++) {
            int k = biA[i];
            const float4* cr = (const float4*)(cbm + (size_t)k * SUBD);
            float dot = 0.f;
#pragma unroll
            for (int i2 = 0; i2 < 16; i2++) {
                float4 c = cr[i2];
                float xa, xb, xc_, xd;
                unpk2(xp0[2*i2],   xa, xb);
                unpk2(xp0[2*i2+1], xc_, xd);
                dot = __fmaf_rn(xa, c.x, dot);  dot = __fmaf_rn(xb, c.y, dot);
                dot = __fmaf_rn(xc_, c.z, dot); dot = __fmaf_rn(xd, c.w, dot);
            }
            float dist = __fadd_rn(__fsub_rn(x2_0, __fmul_rn(2.0f, dot)), sc2[k]);
            if (dist < bd || (dist == bd && k < bk)) { bd = dist; bk = k; }
        }
        winA = bk;
    }
    {
        float bd = 3.4e38f; int bk = 0x7fffffff;
#pragma unroll 1
        for (int i = 0; i < 4; i++) {
            int k = biB[i];
            const float4* cr = (const float4*)(cbm + (size_t)k * SUBD);
            float dot = 0.f;
#pragma unroll
            for (int i2 = 0; i2 < 16; i2++) {
                float4 c = cr[i2];
                float xa, xb, xc_, xd;
                unpk2(xp1[2*i2],   xa, xb);
                unpk2(xp1[2*i2+1], xc_, xd);
                dot = __fmaf_rn(xa, c.x, dot);  dot = __fmaf_rn(xb, c.y, dot);
                dot = __fmaf_rn(xc_, c.z, dot); dot = __fmaf_rn(xd, c.w, dot);
            }
            float dist = __fadd_rn(__fsub_rn(x2_1, __fmul_rn(2.0f, dot)), sc2[k]);
            if (dist < bd || (dist == bd && k < bk)) { bd = dist; bk = k; }
        }
        winB = bk;
    }

    // ---- gather winners + write outputs ----
    const size_t QELEMS = (size_t)NTOK * EMBD;
    {
        const float4* w = (const float4*)(cbm + (size_t)winA * SUBD);
        float4* q = (float4*)(out + (size_t)t0 * EMBD + m * SUBD);
#pragma unroll
        for (int i = 0; i < 16; i++) q[i] = w[i];
        out[QELEMS + (size_t)t0 * NUM_SUB + m] = (float)winA;
    }
    {
        const float4* w = (const float4*)(cbm + (size_t)winB * SUBD);
        float4* q = (float4*)(out + (size_t)t1 * EMBD + m * SUBD);
#pragma unroll
        for (int i = 0; i < 16; i++) q[i] = w[i];
        out[QELEMS + (size_t)t1 * NUM_SUB + m] = (float)winB;
    }
}

extern "C" void kernel_launch(void* const* d_in, const int* in_sizes, int n_in,
                              void* d_out, int out_size)
{
    const float* emb = (const float*)d_in[0];  // [8,2048,1024] f32
    const float* cb  = (const float*)d_in[1];  // [16,1024,64]  f32
    dim3 grid(NTOK / (2 * TPB), NUM_SUB);      // (64, 16)
    pq_argmin_kernel<<<grid, TPB>>>(emb, cb, (float*)d_out);
}